// round 10
// baseline (speedup 1.0000x reference)
#include <cuda_runtime.h>
#include <cuda_bf16.h>
#include <cstdint>

// Problem constants
#define NBM   64      // B*M = 2*32
#define LSEQ  512
#define CDIM  512
#define NH    8
#define HD    64
#define NROWS (NBM*LSEQ)   // 32768

// Scratch (all tf32-rounded; mma k-dims perm16'd within 16-groups):
__device__ float g_xt[NROWS*CDIM];       // X rows, k perm16
__device__ float g_q[NBM*NH*LSEQ*HD];    // [bm][h][l][d''] d perm16
__device__ float g_k[NBM*NH*LSEQ*HD];    // [bm][h][l][d''] d perm16
__device__ float g_v[NBM*NH*HD*LSEQ];    // [bm][h][d][l''] l perm16
__device__ float g_wt[3*CDIM*CDIM];      // [3][n][k''] k perm16

// perm16: logical v -> 4*(v&3) + ((v>>2)&1) + 2*((v>>3)&1).
// LDS.128 at 16*ksp + 4*t then yields {ksA:t, ksA:t+4, ksB:t, ksB:t+4}.
__device__ __forceinline__ int p16(int v) {
    return 4 * (v & 3) + ((v >> 2) & 1) + 2 * ((v >> 3) & 1);
}

__device__ __forceinline__ unsigned f2tf(float f) {
    unsigned u;
    asm("cvt.rna.tf32.f32 %0, %1;" : "=r"(u) : "f"(f));
    return u;
}
__device__ __forceinline__ float f2tff(float f) { return __uint_as_float(f2tf(f)); }

__device__ __forceinline__ void mma_tf32(float* c, const unsigned* a, const unsigned* b) {
    asm("mma.sync.aligned.m16n8k8.row.col.f32.tf32.tf32.f32 "
        "{%0,%1,%2,%3}, {%4,%5,%6,%7}, {%8,%9}, {%0,%1,%2,%3};"
        : "+f"(c[0]), "+f"(c[1]), "+f"(c[2]), "+f"(c[3])
        : "r"(a[0]), "r"(a[1]), "r"(a[2]), "r"(a[3]),
          "r"(b[0]), "r"(b[1]));
}

__device__ __forceinline__ uint32_t smem_u32(const void* p) {
    uint32_t a;
    asm("{ .reg .u64 t; cvta.to.shared.u64 t, %1; cvt.u32.u64 %0, t; }" : "=r"(a) : "l"(p));
    return a;
}

#define CP16(dst, src) \
    asm volatile("cp.async.cg.shared.global [%0], [%1], 16;" :: "r"(dst), "l"(src) : "memory")
#define CP_COMMIT() asm volatile("cp.async.commit_group;" ::: "memory")
#define CP_WAIT(n)  asm volatile("cp.async.wait_group %0;" :: "n"(n) : "memory")

// ---------------------------------------------------------------------------
// Pre-pass A: g_xt = rna_tf32(x), k perm16'd.
// ---------------------------------------------------------------------------
__global__ __launch_bounds__(256) void xt_kernel(const float* __restrict__ x)
{
    int idx = blockIdx.x * 256 + threadIdx.x;          // float4 index
    float4 v = ((const float4*)x)[idx];
    int fbase = idx * 4;
    int grp   = fbase & ~15;
    int start = (fbase >> 2) & 3;
    float* dst = g_xt + grp + start;
    dst[0]  = f2tff(v.x);
    dst[4]  = f2tff(v.y);
    dst[8]  = f2tff(v.z);
    dst[12] = f2tff(v.w);
}

// ---------------------------------------------------------------------------
// Pre-pass B: Wt[mat][n][k''] = rna_tf32(W[k][n]), k perm16'd.
// ---------------------------------------------------------------------------
__global__ __launch_bounds__(256) void wt_kernel(
    const float* __restrict__ Wq, const float* __restrict__ Wk,
    const float* __restrict__ Wv)
{
    __shared__ float s[32][33];
    const float* W = (blockIdx.z == 0) ? Wq : (blockIdx.z == 1) ? Wk : Wv;
    const int k0 = blockIdx.x * 32, n0 = blockIdx.y * 32;
    const int tid = threadIdx.x;
    {
        int kl = tid >> 3, n4 = tid & 7;
        float4 v = *(const float4*)&W[(size_t)(k0 + kl) * CDIM + n0 + n4 * 4];
        s[kl][n4 * 4 + 0] = f2tff(v.x);
        s[kl][n4 * 4 + 1] = f2tff(v.y);
        s[kl][n4 * 4 + 2] = f2tff(v.z);
        s[kl][n4 * 4 + 3] = f2tff(v.w);
    }
    __syncthreads();
    {
        int nl = tid >> 3, k4 = tid & 7;
        float* rowp = g_wt + ((size_t)(blockIdx.z * CDIM + n0 + nl)) * CDIM;
        #pragma unroll
        for (int j = 0; j < 4; j++) {
            int kk = k0 + k4 * 4 + j;
            int kp = (kk & ~15) | p16(kk & 15);
            rowp[kp] = s[k4 * 4 + j][nl];
        }
    }
}

// ---------------------------------------------------------------------------
// Kernel 1: QKV projection. CTA 128x128, 8 warps (2m x 4n, 64x32 each).
// K=512 in 32 stages of 16, 4-deep cp.async pipeline, 2 CTAs/SM.
// ---------------------------------------------------------------------------
#define QKV_TILEA 2048                   // floats: 128 rows x 16
#define QKV_STAGE (2*QKV_TILEA)          // A + B
#define QKV_SMEMB (4*QKV_STAGE*4)        // 65536 bytes

__global__ __launch_bounds__(256, 2) void qkv_v5(
    const float* __restrict__ bq, const float* __restrict__ bk,
    const float* __restrict__ bv)
{
    extern __shared__ float smem[];
    const uint32_t sbase = smem_u32(smem);

    const int tid  = threadIdx.x;
    const int lane = tid & 31;
    const int warp = tid >> 5;
    const int g    = lane >> 2;
    const int t    = lane & 3;
    const int wm   = (warp >> 2) * 64;
    const int wn   = (warp & 3) * 32;

    const int ntile = blockIdx.x;        // 0..11
    const int mat   = ntile >> 2;
    const int col0  = (ntile & 3) * 128;
    const int r0    = blockIdx.y * 128;
    const float* bias = (mat == 0) ? bq : (mat == 1) ? bk : bv;

    const int srow = tid >> 2;           // 0..63
    const int sc   = tid & 3;
    const float* xsrc = g_xt + (size_t)(r0 + srow) * CDIM + sc * 4;
    const float* wsrc = g_wt + (size_t)(mat * CDIM + col0 + srow) * CDIM + sc * 4;
    const uint32_t sOff = (uint32_t)(srow * 16 + sc * 4) * 4;

    auto stage = [&](int kt, int s) {
        const uint32_t aB = sbase + (uint32_t)s * (QKV_STAGE * 4) + sOff;
        const float* xs = xsrc + kt * 16;
        const float* ws = wsrc + kt * 16;
        CP16(aB,                          xs);
        CP16(aB + 64 * 16 * 4,            xs + (size_t)64 * CDIM);
        CP16(aB + QKV_TILEA * 4,          ws);
        CP16(aB + (QKV_TILEA + 64*16)*4,  ws + (size_t)64 * CDIM);
        CP_COMMIT();
    };

    float acc[4][4][4];
    #pragma unroll
    for (int mi = 0; mi < 4; mi++)
        #pragma unroll
        for (int ni = 0; ni < 4; ni++)
            #pragma unroll
            for (int e = 0; e < 4; e++) acc[mi][ni][e] = 0.f;

    stage(0, 0); stage(1, 1); stage(2, 2);

    for (int kt = 0; kt < 32; kt++) {
        CP_WAIT(2);
        __syncthreads();
        if (kt + 3 < 32) stage(kt + 3, (kt + 3) & 3);
        else             CP_COMMIT();     // keep group count uniform

        const unsigned* As = (const unsigned*)(smem + (kt & 3) * QKV_STAGE);
        const unsigned* Bs = As + QKV_TILEA;

        unsigned aA[4][4], aB2[4][4];
        #pragma unroll
        for (int mi = 0; mi < 4; mi++) {
            int rb = wm + mi * 16 + g;
            uint4 lo = *(const uint4*)&As[rb * 16 + 4 * t];
            uint4 hi = *(const uint4*)&As[(rb + 8) * 16 + 4 * t];
            aA[mi][0] = lo.x; aA[mi][1] = hi.x; aA[mi][2] = lo.y; aA[mi][3] = hi.y;
            aB2[mi][0] = lo.z; aB2[mi][1] = hi.z; aB2[mi][2] = lo.w; aB2[mi][3] = hi.w;
        }
        #pragma unroll
        for (int ni = 0; ni < 4; ni++) {
            uint4 u = *(const uint4*)&Bs[(wn + ni * 8 + g) * 16 + 4 * t];
            unsigned bA[2] = { u.x, u.y }, bB[2] = { u.z, u.w };
            #pragma unroll
            for (int mi = 0; mi < 4; mi++) {
                mma_tf32(acc[mi][ni], aA[mi],  bA);
                mma_tf32(acc[mi][ni], aB2[mi], bB);
            }
        }
    }

    // Epilogue: bias + tf32 round + perm16 scatter
    float* qk = (mat == 0) ? g_q : g_k;
    #pragma unroll
    for (int mi = 0; mi < 4; mi++) {
        #pragma unroll
        for (int ep = 0; ep < 2; ep++) {
            int row = wm + mi * 16 + g + ep * 8;
            int R = r0 + row;
            int bm = R >> 9, l = R & 511;
            int lp = (l & ~15) | p16(l & 15);
            #pragma unroll
            for (int ni = 0; ni < 4; ni++) {
                int c = col0 + wn + ni * 8 + t * 2;
                int h = c >> 6, d = c & 63;
                float v0 = f2tff(acc[mi][ni][2 * ep]     + bias[c]);
                float v1 = f2tff(acc[mi][ni][2 * ep + 1] + bias[c + 1]);
                if (mat < 2) {
                    float* base = qk + (((size_t)(bm * NH + h)) * LSEQ + l) * HD;
                    base[(d & ~15) | p16(d & 15)]             = v0;
                    base[((d + 1) & ~15) | p16((d + 1) & 15)] = v1;
                } else {
                    size_t base = ((size_t)(bm * NH + h)) * HD;
                    g_v[(base + d)     * LSEQ + lp] = v0;
                    g_v[(base + d + 1) * LSEQ + lp] = v1;
                }
            }
        }
    }
}

// ---------------------------------------------------------------------------
// Kernel 2: flash attention. CTA = 128 q-rows (8 warps x 16 rows), j-tiles of
// 64 keys. 2 CTAs/SM (<=128 regs). Q frags via LDG (L2-resident).
// O^T = V^T P^T, P built in-register via shuffles (no P smem).
// smem = K[2] + V[2] 64x64 tiles (80 KB).
// ---------------------------------------------------------------------------
#define KST 80
#define KS_OFF(b) ((b) * 64 * KST)
#define VS_OFF(b) (2 * 64 * KST + (b) * 64 * KST)
#define ATTN_FLOATS (4 * 64 * KST)
#define ATTN_SMEMB  (ATTN_FLOATS * 4)    // 81920 bytes

__global__ __launch_bounds__(256, 2) void attn_kernel(float* __restrict__ out)
{
    extern __shared__ float asmem[];
    const uint32_t sbase = smem_u32(asmem);

    const int l0 = blockIdx.x * 128;     // q-tile base
    const int h  = blockIdx.y;
    const int bm = blockIdx.z;

    const int tid  = threadIdx.x;
    const int lane = tid & 31;
    const int warp = tid >> 5;
    const int g    = lane >> 2;
    const int t    = lane & 3;
    const int wr   = warp * 16;          // warp's 16 q-rows

    const float* qb = g_q + ((size_t)(bm * NH + h)) * LSEQ * HD;
    const float* kb = g_k + ((size_t)(bm * NH + h)) * LSEQ * HD;
    const float* vb = g_v + ((size_t)(bm * NH + h)) * HD * LSEQ;

    // ---- stage K0 + V0 ----
    #pragma unroll
    for (int i = 0; i < 4; i++) {
        int idx = tid + i * 256;         // 1024 chunks: 64x64 floats
        int row = idx >> 4, c = idx & 15;
        uint32_t dst = sbase + (uint32_t)(KS_OFF(0) + row * KST + c * 4) * 4;
        CP16(dst, kb + (size_t)row * HD + c * 4);
    }
    #pragma unroll
    for (int i = 0; i < 4; i++) {
        int idx = tid + i * 256;
        int row = idx >> 4, c = idx & 15;
        uint32_t dst = sbase + (uint32_t)(VS_OFF(0) + row * KST + c * 4) * 4;
        CP16(dst, vb + (size_t)row * LSEQ + c * 4);
    }
    CP_COMMIT();

    // ---- Q fragments direct from global (perm16'd d) ----
    unsigned qa[8][4];
    #pragma unroll
    for (int ksp = 0; ksp < 4; ksp++) {
        const float* qr = qb + (size_t)(l0 + wr + g) * HD + ksp * 16 + 4 * t;
        uint4 lo = *(const uint4*)qr;
        uint4 hi = *(const uint4*)(qr + 8 * HD);
        qa[2*ksp][0]   = lo.x; qa[2*ksp][1]   = hi.x;
        qa[2*ksp][2]   = lo.y; qa[2*ksp][3]   = hi.y;
        qa[2*ksp+1][0] = lo.z; qa[2*ksp+1][1] = hi.z;
        qa[2*ksp+1][2] = lo.w; qa[2*ksp+1][3] = hi.w;
    }

    // O^T accumulators: oacc[mi_d][nq]: c0=(d=16mi+g, q=8nq+2t), c1=(d,q+1),
    // c2=(d+8,q), c3=(d+8,q+1)
    float oacc[4][2][4];
    #pragma unroll
    for (int mi = 0; mi < 4; mi++)
        #pragma unroll
        for (int nq = 0; nq < 2; nq++)
            #pragma unroll
            for (int e = 0; e < 4; e++) oacc[mi][nq][e] = 0.f;

    float mrow[2] = { -3.0e38f, -3.0e38f };   // rows wr+g, wr+g+8
    float lsum[2] = { 0.f, 0.f };
    const float kInv = 1.4426950408889634f * 0.125f;  // log2(e)/sqrt(64)
    const int src0 = (lane & ~3) | (t >> 1);
    const int src1 = src0 + 2;

    CP_WAIT(0);
    __syncthreads();

    for (int j = 0; j < 8; j++) {
        const int b = j & 1;
        if (j < 7) {    // prefetch next K/V into other buffer
            const int jn = (j + 1) * 64;
            #pragma unroll
            for (int i = 0; i < 4; i++) {
                int idx = tid + i * 256;
                int row = idx >> 4, c = idx & 15;
                uint32_t dst = sbase + (uint32_t)(KS_OFF(b ^ 1) + row * KST + c * 4) * 4;
                CP16(dst, kb + (size_t)(jn + row) * HD + c * 4);
            }
            #pragma unroll
            for (int i = 0; i < 4; i++) {
                int idx = tid + i * 256;
                int row = idx >> 4, c = idx & 15;
                uint32_t dst = sbase + (uint32_t)(VS_OFF(b ^ 1) + row * KST + c * 4) * 4;
                CP16(dst, vb + (size_t)row * LSEQ + jn + c * 4);
            }
            CP_COMMIT();
        }

        const unsigned* Ks = (const unsigned*)(asmem + KS_OFF(b));
        const unsigned* Vs = (const unsigned*)(asmem + VS_OFF(b));

        // ---- S = Q K^T : sacc[ni]: rows (wr+g, wr+g+8), keys 8ni+2t(+1)
        float sacc[8][4];
        #pragma unroll
        for (int ni = 0; ni < 8; ni++)
            #pragma unroll
            for (int e = 0; e < 4; e++) sacc[ni][e] = 0.f;

        #pragma unroll
        for (int ksp = 0; ksp < 4; ksp++) {
            #pragma unroll
            for (int ni = 0; ni < 8; ni++) {
                uint4 u = *(const uint4*)&Ks[(ni * 8 + g) * KST + ksp * 16 + 4 * t];
                unsigned bA[2] = { u.x, u.y }, bB[2] = { u.z, u.w };
                mma_tf32(sacc[ni], qa[2*ksp],   bA);
                mma_tf32(sacc[ni], qa[2*ksp+1], bB);
            }
        }

        #pragma unroll
        for (int ni = 0; ni < 8; ni++)
            #pragma unroll
            for (int e = 0; e < 4; e++) sacc[ni][e] *= kInv;

        // ---- online softmax (base 2); sacc -> rounded P ----
        float alpha[2];
        #pragma unroll
        for (int e = 0; e < 2; e++) {
            float mt = -3.0e38f;
            #pragma unroll
            for (int ni = 0; ni < 8; ni++) {
                mt = fmaxf(mt, sacc[ni][2 * e]);
                mt = fmaxf(mt, sacc[ni][2 * e + 1]);
            }
            mt = fmaxf(mt, __shfl_xor_sync(0xffffffffu, mt, 1));
            mt = fmaxf(mt, __shfl_xor_sync(0xffffffffu, mt, 2));
            float mnew = fmaxf(mrow[e], mt);
            alpha[e] = exp2f(mrow[e] - mnew);
            mrow[e]  = mnew;
            float rs = 0.f;
            #pragma unroll
            for (int ni = 0; ni < 8; ni++) {
                float p0 = exp2f(sacc[ni][2 * e]     - mnew);
                float p1 = exp2f(sacc[ni][2 * e + 1] - mnew);
                rs += p0 + p1;
                sacc[ni][2 * e]     = f2tff(p0);
                sacc[ni][2 * e + 1] = f2tff(p1);
            }
            rs += __shfl_xor_sync(0xffffffffu, rs, 1);
            rs += __shfl_xor_sync(0xffffffffu, rs, 2);
            lsum[e] = lsum[e] * alpha[e] + rs;
        }

        // ---- rescale O^T by output-row alphas (rows 8nq+2t, +1) ----
        #pragma unroll
        for (int nq = 0; nq < 2; nq++) {
            float a0 = __shfl_sync(0xffffffffu, alpha[nq], 8 * t);
            float a1 = __shfl_sync(0xffffffffu, alpha[nq], 8 * t + 4);
            #pragma unroll
            for (int mi = 0; mi < 4; mi++) {
                oacc[mi][nq][0] *= a0; oacc[mi][nq][2] *= a0;
                oacc[mi][nq][1] *= a1; oacc[mi][nq][3] *= a1;
            }
        }

        // ---- O^T += V^T P^T (A = V^T from smem, B = P^T via shuffles) ----
        #pragma unroll
        for (int ksp = 0; ksp < 4; ksp++) {
            unsigned aA[4][4], aB[4][4];
            #pragma unroll
            for (int mi = 0; mi < 4; mi++) {
                uint4 lo = *(const uint4*)&Vs[(mi * 16 + g) * KST + ksp * 16 + 4 * t];
                uint4 hi = *(const uint4*)&Vs[(mi * 16 + g + 8) * KST + ksp * 16 + 4 * t];
                aA[mi][0] = lo.x; aA[mi][1] = hi.x; aA[mi][2] = lo.y; aA[mi][3] = hi.y;
                aB[mi][0] = lo.z; aB[mi][1] = hi.z; aB[mi][2] = lo.w; aB[mi][3] = hi.w;
            }
            #pragma unroll
            for (int h2 = 0; h2 < 2; h2++) {
                const int ks = 2 * ksp + h2;
                #pragma unroll
                for (int nq = 0; nq < 2; nq++) {
                    float v00 = __shfl_sync(0xffffffffu, sacc[ks][2 * nq],     src0);
                    float v01 = __shfl_sync(0xffffffffu, sacc[ks][2 * nq + 1], src0);
                    float v10 = __shfl_sync(0xffffffffu, sacc[ks][2 * nq],     src1);
                    float v11 = __shfl_sync(0xffffffffu, sacc[ks][2 * nq + 1], src1);
                    unsigned bf[2];
                    bf[0] = __float_as_uint((t & 1) ? v01 : v00);
                    bf[1] = __float_as_uint((t & 1) ? v11 : v10);
                    #pragma unroll
                    for (int mi = 0; mi < 4; mi++)
                        mma_tf32(oacc[mi][nq], h2 ? aB[mi] : aA[mi], bf);
                }
            }
        }

        if (j < 7) CP_WAIT(0);
        __syncthreads();
    }

    // ---- epilogue: per-row 1/lsum via shuffle, transposed STG ----
    #pragma unroll
    for (int nq = 0; nq < 2; nq++) {
        float L0 = __shfl_sync(0xffffffffu, lsum[nq], 8 * t);
        float L1 = __shfl_sync(0xffffffffu, lsum[nq], 8 * t + 4);
        float inv0 = 1.f / L0, inv1 = 1.f / L1;
        int q0 = l0 + wr + 8 * nq + 2 * t;
        float* o0 = out + ((size_t)bm * LSEQ + q0) * CDIM + h * HD;
        float* o1 = o0 + CDIM;
        #pragma unroll
        for (int mi = 0; mi < 4; mi++) {
            o0[mi * 16 + g]     = oacc[mi][nq][0] * inv0;
            o1[mi * 16 + g]     = oacc[mi][nq][1] * inv1;
            o0[mi * 16 + g + 8] = oacc[mi][nq][2] * inv0;
            o1[mi * 16 + g + 8] = oacc[mi][nq][3] * inv1;
        }
    }
}

extern "C" void kernel_launch(void* const* d_in, const int* in_sizes, int n_in,
                              void* d_out, int out_size)
{
    const float* x  = (const float*)d_in[0];
    const float* Wq = (const float*)d_in[1];
    const float* bq = (const float*)d_in[2];
    const float* Wk = (const float*)d_in[3];
    const float* bk = (const float*)d_in[4];
    const float* Wv = (const float*)d_in[5];
    const float* bv = (const float*)d_in[6];
    float* out = (float*)d_out;

    xt_kernel<<<NROWS * CDIM / 4 / 256, 256>>>(x);
    wt_kernel<<<dim3(16, 16, 3), 256>>>(Wq, Wk, Wv);

    cudaFuncSetAttribute(qkv_v5,
                         cudaFuncAttributeMaxDynamicSharedMemorySize, QKV_SMEMB);
    qkv_v5<<<dim3(12, 256), 256, QKV_SMEMB>>>(bq, bk, bv);

    cudaFuncSetAttribute(attn_kernel,
                         cudaFuncAttributeMaxDynamicSharedMemorySize, ATTN_SMEMB);
    attn_kernel<<<dim3(4, NH, NBM), 256, ATTN_SMEMB>>>(out);
}

// round 11
// speedup vs baseline: 2.3570x; 2.3570x over previous
#include <cuda_runtime.h>
#include <cuda_fp16.h>
#include <cstdint>

// Problem constants
#define NBM   64      // B*M
#define LSEQ  512
#define CDIM  512
#define NH    8
#define HD    64
#define NROWS (NBM*LSEQ)   // 32768

// All scratch stored as uint = half2 pairs, pair-index perm16'd within
// 16-pair (64B) groups. One LDS.128 then yields operand fragments for TWO
// m16n8k16 k-steps: {pair t, t+4, 8+t, 12+t}.
__device__ __align__(16) unsigned g_xt[NROWS*CDIM/2];     // [row][256 k-pairs]
__device__ __align__(16) unsigned g_q [NBM*NH*LSEQ*HD/2]; // [bm][h][l][32 d-pairs], pre-scaled
__device__ __align__(16) unsigned g_k [NBM*NH*LSEQ*HD/2]; // [bm][h][l][32 d-pairs]
__device__ __align__(16) unsigned g_v [NBM*NH*HD*LSEQ/2]; // [bm][h][d][256 l-pairs] (V^T)
__device__ __align__(16) unsigned g_wt[3*CDIM*CDIM/2];    // [mat][n][256 k-pairs]

// perm16 on pair index p (0..15): pos = 4*(p&3) + ((p>>2)&1) + 2*((p>>3)&1)
__device__ __forceinline__ int p16(int v) {
    return 4 * (v & 3) + ((v >> 2) & 1) + 2 * ((v >> 3) & 1);
}

__device__ __forceinline__ unsigned pack2(float a, float b) {
    __half2 h = __floats2half2_rn(a, b);     // .x = a (low half = first element)
    return *reinterpret_cast<unsigned*>(&h);
}

__device__ __forceinline__ float ex2(float x) {
    float r;
    asm("ex2.approx.ftz.f32 %0, %1;" : "=f"(r) : "f"(x));
    return r;
}

__device__ __forceinline__ void mma_f16(float* c, const unsigned* a, const unsigned* b) {
    asm("mma.sync.aligned.m16n8k16.row.col.f32.f16.f16.f32 "
        "{%0,%1,%2,%3}, {%4,%5,%6,%7}, {%8,%9}, {%0,%1,%2,%3};"
        : "+f"(c[0]), "+f"(c[1]), "+f"(c[2]), "+f"(c[3])
        : "r"(a[0]), "r"(a[1]), "r"(a[2]), "r"(a[3]),
          "r"(b[0]), "r"(b[1]));
}

__device__ __forceinline__ uint32_t smem_u32(const void* p) {
    uint32_t a;
    asm("{ .reg .u64 t; cvta.to.shared.u64 t, %1; cvt.u32.u64 %0, t; }" : "=r"(a) : "l"(p));
    return a;
}

#define CP16(dst, src) \
    asm volatile("cp.async.cg.shared.global [%0], [%1], 16;" :: "r"(dst), "l"(src) : "memory")
#define CP_COMMIT() asm volatile("cp.async.commit_group;" ::: "memory")
#define CP_WAIT(n)  asm volatile("cp.async.wait_group %0;" :: "n"(n) : "memory")

// ---------------------------------------------------------------------------
// Pre-pass A: g_xt = fp16(x) pairs, pair-perm'd.
// ---------------------------------------------------------------------------
__global__ __launch_bounds__(256) void xt_kernel(const float* __restrict__ x)
{
    int p = blockIdx.x * 256 + threadIdx.x;        // global pair index
    float2 v = ((const float2*)x)[p];
    g_xt[(p & ~15) | p16(p & 15)] = pack2(v.x, v.y);
}

// ---------------------------------------------------------------------------
// Pre-pass B: g_wt[mat][n][k-pairs] = fp16(W^T), pair-perm'd.
// ---------------------------------------------------------------------------
__global__ __launch_bounds__(256) void wt_kernel(
    const float* __restrict__ Wq, const float* __restrict__ Wk,
    const float* __restrict__ Wv)
{
    __shared__ float s[32][33];
    const float* W = (blockIdx.z == 0) ? Wq : (blockIdx.z == 1) ? Wk : Wv;
    const int k0 = blockIdx.x * 32, n0 = blockIdx.y * 32;
    const int tid = threadIdx.x;
    {
        int kl = tid >> 3, n4 = tid & 7;
        float4 v = *(const float4*)&W[(size_t)(k0 + kl) * CDIM + n0 + n4 * 4];
        s[kl][n4 * 4 + 0] = v.x; s[kl][n4 * 4 + 1] = v.y;
        s[kl][n4 * 4 + 2] = v.z; s[kl][n4 * 4 + 3] = v.w;
    }
    __syncthreads();
    {
        int nl = tid >> 3, k4 = tid & 7;
        unsigned uA = pack2(s[k4 * 4 + 0][nl], s[k4 * 4 + 1][nl]);
        unsigned uB = pack2(s[k4 * 4 + 2][nl], s[k4 * 4 + 3][nl]);
        size_t base = (size_t)(blockIdx.z * CDIM + n0 + nl) * 256;
        int pA = (k0 >> 1) + k4 * 2, pB = pA + 1;
        g_wt[base + ((pA & ~15) | p16(pA & 15))] = uA;
        g_wt[base + ((pB & ~15) | p16(pB & 15))] = uB;
    }
}

// ---------------------------------------------------------------------------
// Kernel 1: QKV projection, fp16 m16n8k16. CTA 128x128, 8 warps (2m x 4n).
// K=512 halves in 16 stages of 32, 4-deep cp.async pipeline, 2 CTAs/SM.
// Q/K: A = X rows, B = W^T rows. V: A = Wv^T rows (d), B = X rows (l)
//   -> D = V^T directly, so epilogue pairs fall along l.
// ---------------------------------------------------------------------------
#define QKV_TILEA 2048                   // uints: 128 rows x 16
#define QKV_STAGE (2*QKV_TILEA)          // A + B = 4096 uints = 16KB
#define QKV_SMEMB (4*QKV_STAGE*4)        // 65536 bytes

__global__ __launch_bounds__(256, 2) void qkv_f16(
    const float* __restrict__ bq, const float* __restrict__ bk,
    const float* __restrict__ bv)
{
    extern __shared__ unsigned smem[];
    const uint32_t sbase = smem_u32(smem);

    const int tid  = threadIdx.x;
    const int lane = tid & 31;
    const int warp = tid >> 5;
    const int g    = lane >> 2;
    const int t    = lane & 3;
    const int wm   = (warp >> 2) * 64;
    const int wn   = (warp & 3) * 32;

    const int gx = blockIdx.x;           // 0..11
    const int gy = blockIdx.y;           // 0..255
    const bool isV = gx >= 8;
    const int mat  = isV ? 2 : (gx >> 2);
    const int col0 = isV ? 0 : (gx & 3) * 128;
    const int d0   = isV ? (gx - 8) * 128 : 0;
    const int r0   = gy * 128;

    const unsigned* Asrc;
    const unsigned* Bsrc;
    if (!isV) {
        Asrc = g_xt + (size_t)r0 * 256;
        Bsrc = g_wt + (size_t)(mat * CDIM + col0) * 256;
    } else {
        Asrc = g_wt + (size_t)(2 * CDIM + d0) * 256;
        Bsrc = g_xt + (size_t)r0 * 256;
    }
    const float* bias = (mat == 0) ? bq : (mat == 1) ? bk : bv;

    // staging: 4 CP16/thread/stage (A 512 chunks + B 512 chunks)
    const int srow = tid >> 1;           // 0..127
    const int sc   = tid & 1;
    const unsigned* aS = Asrc + (size_t)srow * 256 + sc * 8;
    const unsigned* bS = Bsrc + (size_t)srow * 256 + sc * 8;
    const uint32_t sOff = (uint32_t)(srow * 16 + sc * 8) * 4;

    auto stage = [&](int kt, int s) {
        uint32_t dA = sbase + (uint32_t)s * (QKV_STAGE * 4) + sOff;
        uint32_t dB = dA + QKV_TILEA * 4;
        const unsigned* sa = aS + kt * 16;
        const unsigned* sb = bS + kt * 16;
        CP16(dA, sa); CP16(dA + 16, sa + 4);
        CP16(dB, sb); CP16(dB + 16, sb + 4);
        CP_COMMIT();
    };

    float acc[4][4][4];
    #pragma unroll
    for (int mi = 0; mi < 4; mi++)
        #pragma unroll
        for (int ni = 0; ni < 4; ni++)
            #pragma unroll
            for (int e = 0; e < 4; e++) acc[mi][ni][e] = 0.f;

    stage(0, 0); stage(1, 1); stage(2, 2);

    for (int kt = 0; kt < 16; kt++) {
        CP_WAIT(2);
        __syncthreads();
        if (kt + 3 < 16) stage(kt + 3, (kt + 3) & 3);
        else             CP_COMMIT();

        const unsigned* As = smem + (kt & 3) * QKV_STAGE;
        const unsigned* Bs = As + QKV_TILEA;

        unsigned a0[4][4], a1[4][4];
        #pragma unroll
        for (int mi = 0; mi < 4; mi++) {
            int rb = wm + mi * 16 + g;
            uint4 lo = *(const uint4*)&As[rb * 16 + 4 * t];
            uint4 hi = *(const uint4*)&As[(rb + 8) * 16 + 4 * t];
            a0[mi][0] = lo.x; a0[mi][1] = hi.x; a0[mi][2] = lo.y; a0[mi][3] = hi.y;
            a1[mi][0] = lo.z; a1[mi][1] = hi.z; a1[mi][2] = lo.w; a1[mi][3] = hi.w;
        }
        #pragma unroll
        for (int ni = 0; ni < 4; ni++) {
            uint4 u = *(const uint4*)&Bs[(wn + ni * 8 + g) * 16 + 4 * t];
            unsigned b0[2] = { u.x, u.y }, b1[2] = { u.z, u.w };
            #pragma unroll
            for (int mi = 0; mi < 4; mi++) {
                mma_f16(acc[mi][ni], a0[mi], b0);
                mma_f16(acc[mi][ni], a1[mi], b1);
            }
        }
    }
    __syncthreads();

    // Epilogue
    const float kInv = 1.4426950408889634f * 0.125f;  // log2(e)/sqrt(64), folded into Q
    unsigned* qk = (mat == 0) ? g_q : g_k;

    #pragma unroll
    for (int mi = 0; mi < 4; mi++) {
        #pragma unroll
        for (int ep = 0; ep < 2; ep++) {
            int rowD = wm + mi * 16 + g + ep * 8;
            #pragma unroll
            for (int ni = 0; ni < 4; ni++) {
                float v0 = acc[mi][ni][2 * ep];
                float v1 = acc[mi][ni][2 * ep + 1];
                if (!isV) {
                    int R = r0 + rowD;
                    int bm = R >> 9, l = R & 511;
                    int c = col0 + wn + ni * 8 + t * 2;
                    int h = c >> 6, d = c & 63;
                    v0 += bias[c]; v1 += bias[c + 1];
                    if (mat == 0) { v0 *= kInv; v1 *= kInv; }
                    int dp = d >> 1;
                    int pos = (dp & ~15) | p16(dp & 15);
                    qk[((size_t)(bm * NH + h) * LSEQ + l) * 32 + pos] = pack2(v0, v1);
                } else {
                    int dg = d0 + rowD;              // 0..511
                    int h = dg >> 6, d = dg & 63;
                    int lc = wn + ni * 8 + t * 2;
                    int L = r0 + lc;
                    int bm = L >> 9, ll = L & 511;
                    float bv_ = bias[dg];
                    v0 += bv_; v1 += bv_;
                    int lp = ll >> 1;
                    int pos = (lp & ~15) | p16(lp & 15);
                    g_v[((size_t)(bm * NH + h) * HD + d) * 256 + pos] = pack2(v0, v1);
                }
            }
        }
    }
}

// ---------------------------------------------------------------------------
// Kernel 2: flash attention, fp16 m16n8k16. CTA 128 q-rows (8 warps x 16),
// 64-key j-tiles double-buffered, 2 CTAs/SM. Q frags via LDG.
// O^T = V^T P^T with P fragments SELF-OWNED (zero shuffles).
// smem: K[2] + V[2] 64-row tiles, stride 48 uints (conflict-free).
// ---------------------------------------------------------------------------
#define AST 48
#define KS_OFF(b) ((b) * 64 * AST)
#define VS_OFF(b) (2 * 64 * AST + (b) * 64 * AST)
#define ATTN_SMEMB (4 * 64 * AST * 4)    // 49152 bytes

__global__ __launch_bounds__(256, 2) void attn_kernel(float* __restrict__ out)
{
    extern __shared__ unsigned asmem[];
    const uint32_t sbase = smem_u32(asmem);

    const int l0 = blockIdx.x * 128;
    const int h  = blockIdx.y;
    const int bm = blockIdx.z;

    const int tid  = threadIdx.x;
    const int lane = tid & 31;
    const int warp = tid >> 5;
    const int g    = lane >> 2;
    const int t    = lane & 3;
    const int wr   = warp * 16;

    const unsigned* qb = g_q + (size_t)(bm * NH + h) * LSEQ * 32;
    const unsigned* kb = g_k + (size_t)(bm * NH + h) * LSEQ * 32;
    const unsigned* vb = g_v + (size_t)(bm * NH + h) * HD * 256;

    const int sr = tid >> 2, sch = tid & 3;   // staging: 64 rows x 4 thread-chunks

    // ---- stage K0 + V0 ----
    {
        uint32_t dK = sbase + (uint32_t)(KS_OFF(0) + sr * AST + sch * 8) * 4;
        const unsigned* sK = kb + (size_t)sr * 32 + sch * 8;
        CP16(dK, sK); CP16(dK + 16, sK + 4);
        uint32_t dV = sbase + (uint32_t)(VS_OFF(0) + sr * AST + sch * 8) * 4;
        const unsigned* sV = vb + (size_t)sr * 256 + sch * 8;
        CP16(dV, sV); CP16(dV + 16, sV + 4);
        CP_COMMIT();
    }

    // ---- Q fragments via LDG (Q pre-scaled by log2(e)/8) ----
    unsigned qa[4][4];
    {
        const unsigned* p0 = qb + (size_t)(l0 + wr + g) * 32 + 4 * t;
        const unsigned* p8 = qb + (size_t)(l0 + wr + g + 8) * 32 + 4 * t;
        uint4 A0 = *(const uint4*)p0;
        uint4 A1 = *(const uint4*)(p0 + 16);
        uint4 B0 = *(const uint4*)p8;
        uint4 B1 = *(const uint4*)(p8 + 16);
        qa[0][0] = A0.x; qa[0][1] = B0.x; qa[0][2] = A0.y; qa[0][3] = B0.y;
        qa[1][0] = A0.z; qa[1][1] = B0.z; qa[1][2] = A0.w; qa[1][3] = B0.w;
        qa[2][0] = A1.x; qa[2][1] = B1.x; qa[2][2] = A1.y; qa[2][3] = B1.y;
        qa[3][0] = A1.z; qa[3][1] = B1.z; qa[3][2] = A1.w; qa[3][3] = B1.w;
    }

    float oacc[4][2][4];
    #pragma unroll
    for (int mi = 0; mi < 4; mi++)
        #pragma unroll
        for (int nq = 0; nq < 2; nq++)
            #pragma unroll
            for (int e = 0; e < 4; e++) oacc[mi][nq][e] = 0.f;

    float mrow[2] = { -3.0e38f, -3.0e38f };
    float lsum[2] = { 0.f, 0.f };

    CP_WAIT(0);
    __syncthreads();

    for (int j = 0; j < 8; j++) {
        const int b = j & 1;
        if (j < 7) {
            const int jn = (j + 1) * 64;
            uint32_t dK = sbase + (uint32_t)(KS_OFF(b ^ 1) + sr * AST + sch * 8) * 4;
            const unsigned* sK = kb + (size_t)(jn + sr) * 32 + sch * 8;
            CP16(dK, sK); CP16(dK + 16, sK + 4);
            uint32_t dV = sbase + (uint32_t)(VS_OFF(b ^ 1) + sr * AST + sch * 8) * 4;
            const unsigned* sV = vb + (size_t)sr * 256 + (jn >> 1) + sch * 8;
            CP16(dV, sV); CP16(dV + 16, sV + 4);
            CP_COMMIT();
        }

        const unsigned* Ks = asmem + KS_OFF(b);
        const unsigned* Vs = asmem + VS_OFF(b);

        // ---- S = Q K^T (in log2 domain; scale folded into Q) ----
        float sacc[8][4];
        #pragma unroll
        for (int ni = 0; ni < 8; ni++)
            #pragma unroll
            for (int e = 0; e < 4; e++) sacc[ni][e] = 0.f;

        #pragma unroll
        for (int ni = 0; ni < 8; ni++) {
            const unsigned* kr = Ks + (8 * ni + g) * AST + 4 * t;
            uint4 u0 = *(const uint4*)kr;
            uint4 u1 = *(const uint4*)(kr + 16);
            unsigned b0[2] = { u0.x, u0.y }, b1[2] = { u0.z, u0.w };
            unsigned b2[2] = { u1.x, u1.y }, b3[2] = { u1.z, u1.w };
            mma_f16(sacc[ni], qa[0], b0);
            mma_f16(sacc[ni], qa[1], b1);
            mma_f16(sacc[ni], qa[2], b2);
            mma_f16(sacc[ni], qa[3], b3);
        }

        // ---- online softmax (base 2); P packed as fp16 pairs, self-owned ----
        unsigned pp[8][2];
        float alpha[2];
        #pragma unroll
        for (int e = 0; e < 2; e++) {
            float mt = -3.0e38f;
            #pragma unroll
            for (int ni = 0; ni < 8; ni++) {
                mt = fmaxf(mt, sacc[ni][2 * e]);
                mt = fmaxf(mt, sacc[ni][2 * e + 1]);
            }
            mt = fmaxf(mt, __shfl_xor_sync(0xffffffffu, mt, 1));
            mt = fmaxf(mt, __shfl_xor_sync(0xffffffffu, mt, 2));
            float mnew = fmaxf(mrow[e], mt);
            alpha[e] = ex2(mrow[e] - mnew);
            mrow[e]  = mnew;
            float rs = 0.f;
            #pragma unroll
            for (int ni = 0; ni < 8; ni++) {
                float p0 = ex2(sacc[ni][2 * e]     - mnew);
                float p1 = ex2(sacc[ni][2 * e + 1] - mnew);
                rs += p0 + p1;
                pp[ni][e] = pack2(p0, p1);
            }
            rs += __shfl_xor_sync(0xffffffffu, rs, 1);
            rs += __shfl_xor_sync(0xffffffffu, rs, 2);
            lsum[e] = lsum[e] * alpha[e] + rs;
        }

        // ---- rescale O^T by output-row alphas ----
        #pragma unroll
        for (int nq = 0; nq < 2; nq++) {
            float a0 = __shfl_sync(0xffffffffu, alpha[nq], 8 * t);
            float a1 = __shfl_sync(0xffffffffu, alpha[nq], 8 * t + 4);
            #pragma unroll
            for (int mi = 0; mi < 4; mi++) {
                oacc[mi][nq][0] *= a0; oacc[mi][nq][2] *= a0;
                oacc[mi][nq][1] *= a1; oacc[mi][nq][3] *= a1;
            }
        }

        // ---- O^T += V^T P^T (P fragments = lane's own pp, NO shuffles) ----
        #pragma unroll
        for (int mi = 0; mi < 4; mi++) {
            const unsigned* vr  = Vs + (16 * mi + g) * AST + 4 * t;
            const unsigned* vr8 = Vs + (16 * mi + g + 8) * AST + 4 * t;
            {
                uint4 lo = *(const uint4*)vr;
                uint4 hi = *(const uint4*)vr8;
                unsigned a0[4] = { lo.x, hi.x, lo.y, hi.y };
                unsigned a1[4] = { lo.z, hi.z, lo.w, hi.w };
                #pragma unroll
                for (int nq = 0; nq < 2; nq++) {
                    unsigned bb0[2] = { pp[0][nq], pp[1][nq] };
                    mma_f16(oacc[mi][nq], a0, bb0);
                    unsigned bb1[2] = { pp[2][nq], pp[3][nq] };
                    mma_f16(oacc[mi][nq], a1, bb1);
                }
            }
            {
                uint4 lo = *(const uint4*)(vr + 16);
                uint4 hi = *(const uint4*)(vr8 + 16);
                unsigned a2[4] = { lo.x, hi.x, lo.y, hi.y };
                unsigned a3[4] = { lo.z, hi.z, lo.w, hi.w };
                #pragma unroll
                for (int nq = 0; nq < 2; nq++) {
                    unsigned bb2[2] = { pp[4][nq], pp[5][nq] };
                    mma_f16(oacc[mi][nq], a2, bb2);
                    unsigned bb3[2] = { pp[6][nq], pp[7][nq] };
                    mma_f16(oacc[mi][nq], a3, bb3);
                }
            }
        }

        if (j < 7) CP_WAIT(0);
        __syncthreads();
    }

    // ---- epilogue: per-row 1/lsum via shuffle, transposed STG ----
    #pragma unroll
    for (int nq = 0; nq < 2; nq++) {
        float L0 = __shfl_sync(0xffffffffu, lsum[nq], 8 * t);
        float L1 = __shfl_sync(0xffffffffu, lsum[nq], 8 * t + 4);
        float inv0 = 1.f / L0, inv1 = 1.f / L1;
        int q0 = l0 + wr + 8 * nq + 2 * t;
        float* o0 = out + ((size_t)bm * LSEQ + q0) * CDIM + h * HD;
        float* o1 = o0 + CDIM;
        #pragma unroll
        for (int mi = 0; mi < 4; mi++) {
            o0[mi * 16 + g]     = oacc[mi][nq][0] * inv0;
            o1[mi * 16 + g]     = oacc[mi][nq][1] * inv1;
            o0[mi * 16 + g + 8] = oacc[mi][nq][2] * inv0;
            o1[mi * 16 + g + 8] = oacc[mi][nq][3] * inv1;
        }
    }
}

extern "C" void kernel_launch(void* const* d_in, const int* in_sizes, int n_in,
                              void* d_out, int out_size)
{
    const float* x  = (const float*)d_in[0];
    const float* Wq = (const float*)d_in[1];
    const float* bq = (const float*)d_in[2];
    const float* Wk = (const float*)d_in[3];
    const float* bk = (const float*)d_in[4];
    const float* Wv = (const float*)d_in[5];
    const float* bv = (const float*)d_in[6];
    float* out = (float*)d_out;

    xt_kernel<<<NROWS * CDIM / 2 / 256, 256>>>(x);
    wt_kernel<<<dim3(16, 16, 3), 256>>>(Wq, Wk, Wv);

    cudaFuncSetAttribute(qkv_f16,
                         cudaFuncAttributeMaxDynamicSharedMemorySize, QKV_SMEMB);
    qkv_f16<<<dim3(12, 256), 256, QKV_SMEMB>>>(bq, bk, bv);

    cudaFuncSetAttribute(attn_kernel,
                         cudaFuncAttributeMaxDynamicSharedMemorySize, ATTN_SMEMB);
    attn_kernel<<<dim3(4, NH, NBM), 256, ATTN_SMEMB>>>(out);
}